// round 9
// baseline (speedup 1.0000x reference)
#include <cuda_runtime.h>
#include <cuda_fp16.h>
#include <cstdint>
#include <cstddef>

#define D         256
#define K         1024
#define TP        128
#define NTHREADS  512
#define NBLOCKS   256
#define OUT_ELEMS 8388608
#define XROW      264            // X smem row (halfs): 528B
#define WROWH     72             // W smem row (halfs): 144B
#define EPSILON   1.0f

// ---- vq_score smem byte layout ----
#define OFF_XH    0              // 128*264*2 = 67584
#define OFF_WH0   67584          // 18432
#define OFF_WH1   86016          // 18432
#define OFF_WSQ   104448         // 1024 f32
#define OFF_STAGE 108544         // 128 x 136 halfs = 34816 (row pad kills STS conflicts)
#define SMEM_A    143360
#define OFF_TBUF  OFF_WH0        // 32x132 f32 transpose buffer (X-fill phase only)
#define STAGE_ROW 136            // halfs

__device__ float          g_wsq[K];
__device__ unsigned short g_whi[K * D];
__device__ unsigned short g_scores[32768 * K];   // 64MB fp16 scratch (fits L2)
__device__ float          g_partial[NBLOCKS];
__device__ int            g_count;

__device__ __forceinline__ uint32_t smem_u32(const void* p) {
    uint32_t a;
    asm("{ .reg .u64 t; cvta.to.shared.u64 t, %1; cvt.u32.u64 %0, t; }" : "=r"(a) : "l"(p));
    return a;
}
__device__ __forceinline__ void ldsm4(uint32_t* r, uint32_t addr) {
    asm volatile("ldmatrix.sync.aligned.m8n8.x4.shared.b16 {%0,%1,%2,%3}, [%4];"
                 : "=r"(r[0]), "=r"(r[1]), "=r"(r[2]), "=r"(r[3]) : "r"(addr));
}
__device__ __forceinline__ void mma16816(float* c, const uint32_t* a, const uint32_t* b) {
    asm volatile(
        "mma.sync.aligned.m16n8k16.row.col.f32.f16.f16.f32 "
        "{%0,%1,%2,%3}, {%4,%5,%6,%7}, {%8,%9}, {%0,%1,%2,%3};"
        : "+f"(c[0]), "+f"(c[1]), "+f"(c[2]), "+f"(c[3])
        : "r"(a[0]), "r"(a[1]), "r"(a[2]), "r"(a[3]), "r"(b[0]), "r"(b[1]));
}

// ---- prep: 0.5*||w||^2 + fp16 hi of W (warp per row) ----
__global__ void vq_prep(const float* __restrict__ wgt)
{
    int wid  = threadIdx.x >> 5;
    int lane = threadIdx.x & 31;
    int row  = blockIdx.x * 8 + wid;
    const float4* r = (const float4*)(wgt + (size_t)row * D);
    float4 a = r[lane];
    float4 b = r[lane + 32];
    float s = a.x * a.x;
    s = fmaf(a.y, a.y, s); s = fmaf(a.z, a.z, s); s = fmaf(a.w, a.w, s);
    s = fmaf(b.x, b.x, s); s = fmaf(b.y, b.y, s);
    s = fmaf(b.z, b.z, s); s = fmaf(b.w, b.w, s);
    #pragma unroll
    for (int o = 16; o > 0; o >>= 1) s += __shfl_xor_sync(0xffffffffu, s, o);
    if (lane == 0) g_wsq[row] = 0.5f * s;

    float v[2][4] = {{a.x, a.y, a.z, a.w}, {b.x, b.y, b.z, b.w}};
    #pragma unroll
    for (int h = 0; h < 2; ++h) {
        unsigned short ph[4];
        #pragma unroll
        for (int i = 0; i < 4; ++i)
            ph[i] = __half_as_ushort(__float2half_rn(v[h][i]));
        *(uint2*)(g_whi + (size_t)row * D + h * 128 + lane * 4) = *(uint2*)ph;
    }
}

// ---- kernel A: hi-only fp16 GEMM -> approx scores to global scratch ----
__global__ void __launch_bounds__(NTHREADS, 1)
vq_score(const float* __restrict__ inp)
{
    extern __shared__ char smem[];
    const uint32_t sb = smem_u32(smem);
    float* wsq_s = (float*)(smem + OFF_WSQ);
    float* tbuf  = (float*)(smem + OFF_TBUF);
    unsigned short* Xh    = (unsigned short*)(smem + OFF_XH);
    unsigned short* stage = (unsigned short*)(smem + OFF_STAGE);

    const int tid  = threadIdx.x;
    const int lane = tid & 31;
    const int warp = tid >> 5;
    const int g    = lane >> 2;
    const int t    = lane & 3;
    const int wN   = warp & 3;
    const int wM   = warp >> 2;
    const int mi   = lane >> 3;
    const int mr   = lane & 7;

    const int n0  = blockIdx.x * TP;
    const int b   = n0 >> 10;
    const int hw0 = n0 & 1023;
    const float* xin = inp + (((size_t)b * D) << 10) + hw0;

    wsq_s[tid]       = g_wsq[tid];
    wsq_s[tid + 512] = g_wsq[tid + 512];

    uint32_t aXh[2], rB[2];
    #pragma unroll
    for (int mt = 0; mt < 2; ++mt)
        aXh[mt] = sb + OFF_XH +
            (uint32_t)((wM * 32 + mt * 16 + (mi & 1) * 8 + mr) * XROW + (mi >> 1) * 8) * 2;
    #pragma unroll
    for (int q = 0; q < 2; ++q)
        rB[q] = (uint32_t)((wN * 32 + (q * 2 + (mi >> 1)) * 8 + mr) * WROWH + (mi & 1) * 8) * 2;

    // prefetch W piece 0
    uint4 fh[2];
    #pragma unroll
    for (int j = 0; j < 2; ++j) {
        int idx = tid + j * NTHREADS;
        int code = idx >> 3, seg = idx & 7;
        fh[j] = *(const uint4*)(g_whi + (size_t)code * D + seg * 8);
    }

    // ---- X transpose + fp16 hi, 8 slices of 32 dims ----
    for (int dc = 0; dc < 8; ++dc) {
        {
            int d  = tid >> 4;
            int p0 = (tid & 15) << 3;
            const float* src = xin + (((size_t)(dc * 32 + d)) << 10) + p0;
            float4 v0 = *(const float4*)(src);
            float4 v1 = *(const float4*)(src + 4);
            float* dst = tbuf + d * 132 + p0;
            dst[0]=v0.x; dst[1]=v0.y; dst[2]=v0.z; dst[3]=v0.w;
            dst[4]=v1.x; dst[5]=v1.y; dst[6]=v1.z; dst[7]=v1.w;
        }
        __syncthreads();
        {
            int p  = tid & 127;
            int dq = tid >> 7;
            uint32_t ph[4];
            #pragma unroll
            for (int i = 0; i < 4; ++i) {
                __half h0 = __float2half_rn(tbuf[(dq * 8 + 2 * i    ) * 132 + p]);
                __half h1 = __float2half_rn(tbuf[(dq * 8 + 2 * i + 1) * 132 + p]);
                ph[i] = (uint32_t)__half_as_ushort(h0) | ((uint32_t)__half_as_ushort(h1) << 16);
            }
            *(uint4*)(Xh + p * XROW + dc * 32 + dq * 8) = make_uint4(ph[0], ph[1], ph[2], ph[3]);
        }
        __syncthreads();
    }

    float acc[2][4][4];
    #pragma unroll
    for (int mt = 0; mt < 2; ++mt)
        #pragma unroll
        for (int nt = 0; nt < 4; ++nt)
            #pragma unroll
            for (int j = 0; j < 4; ++j) acc[mt][nt][j] = 0.f;

    for (int piece = 0; piece < 32; ++piece) {
        const int nc   = piece >> 2;
        const int kc   = piece & 3;
        const int bsel = piece & 1;
        unsigned short* WhB = (unsigned short*)(smem + (bsel ? OFF_WH1 : OFF_WH0));

        #pragma unroll
        for (int j = 0; j < 2; ++j) {
            int idx = tid + j * NTHREADS;
            int code = idx >> 3, seg = idx & 7;
            *(uint4*)(WhB + code * WROWH + seg * 8) = fh[j];
        }
        if (piece + 1 < 32) {
            int nn = (piece + 1) >> 2, nk = (piece + 1) & 3;
            #pragma unroll
            for (int j = 0; j < 2; ++j) {
                int idx = tid + j * NTHREADS;
                int code = idx >> 3, seg = idx & 7;
                fh[j] = *(const uint4*)(g_whi + (size_t)(nn * 128 + code) * D + nk * 64 + seg * 8);
            }
        }
        __syncthreads();

        const uint32_t wbh = sb + (bsel ? OFF_WH1 : OFF_WH0);
        const uint32_t ao0 = (uint32_t)kc * 128;
        #pragma unroll
        for (int ks = 0; ks < 4; ++ks) {
            uint32_t ah0[4], ah1[4], bh[8];
            uint32_t ao = ao0 + ks * 32;
            ldsm4(ah0, aXh[0] + ao);
            ldsm4(ah1, aXh[1] + ao);
            ldsm4(bh + 0, wbh + rB[0] + ks * 32);
            ldsm4(bh + 4, wbh + rB[1] + ks * 32);
            #pragma unroll
            for (int nt = 0; nt < 4; ++nt) {
                mma16816(acc[0][nt], ah0, &bh[nt * 2]);
                mma16816(acc[1][nt], ah1, &bh[nt * 2]);
            }
        }

        if (kc == 3) {
            // fold: s = acc - 0.5||w||^2 -> fp16 stage
            #pragma unroll
            for (int mt = 0; mt < 2; ++mt)
                #pragma unroll
                for (int nt = 0; nt < 4; ++nt)
                    #pragma unroll
                    for (int j = 0; j < 4; ++j) {
                        int nl = wN * 32 + nt * 8 + 2 * t + (j & 1);
                        int p  = wM * 32 + mt * 16 + (j >> 1) * 8 + g;
                        float s = acc[mt][nt][j] - wsq_s[nc * 128 + nl];
                        stage[p * STAGE_ROW + nl] = __half_as_ushort(__float2half_rn(s));
                        acc[mt][nt][j] = 0.f;
                    }
            __syncthreads();
            // copy stage -> global scores (coalesced uint4)
            #pragma unroll
            for (int j2 = 0; j2 < 4; ++j2) {
                int idx = tid + j2 * NTHREADS;     // 0..2047
                int p   = idx >> 4, seg = idx & 15;
                uint4 v = *(const uint4*)(stage + p * STAGE_ROW + seg * 8);
                *(uint4*)(g_scores + (size_t)(n0 + p) * K + nc * 128 + seg * 8) = v;
            }
        }
    }
}

// ---- kernel B: scan + exact rescue + gather + NCHW write + loss ----
__global__ void __launch_bounds__(128, 4)
vq_select(const float* __restrict__ inp, const float* __restrict__ wgt,
          float* __restrict__ out, int loss_index)
{
    __shared__ float sred[128];
    __shared__ int   sflg[1];

    const int tid = threadIdx.x;
    const int q   = blockIdx.x * 128 + tid;     // global position
    const int b   = q >> 10;
    const int hw  = q & 1023;
    const float* xp = inp + (((size_t)b * D) << 10) + hw;   // x[d] = xp[d<<10]
    const uint4* srow = (const uint4*)(g_scores + (size_t)q * K);

    // pass 1: approx max
    float smax = -1e30f;
    #pragma unroll 4
    for (int i = 0; i < 128; ++i) {
        uint4 v = __ldg(srow + i);
        const __half2* h2 = (const __half2*)&v;
        #pragma unroll
        for (int j = 0; j < 4; ++j) {
            float2 f = __half22float2(h2[j]);
            smax = fmaxf(smax, fmaxf(f.x, f.y));
        }
    }
    const float thr = smax - EPSILON;

    // pass 2: exact fp32 rescue of candidates (ascending k, strict > => lowest wins)
    float bestv = -1e30f;
    int   besti = 0;
    for (int i = 0; i < 128; ++i) {
        uint4 v = __ldg(srow + i);
        const __half2* h2 = (const __half2*)&v;
        #pragma unroll
        for (int j = 0; j < 8; ++j) {
            float s = __half2float(((const __half*)h2)[j]);
            if (s >= thr) {
                int k = i * 8 + j;
                const float4* wr = (const float4*)(wgt + (size_t)k * D);
                float acc = 0.f;
                #pragma unroll 4
                for (int gq = 0; gq < 64; ++gq) {
                    float4 w4 = __ldg(wr + gq);
                    acc = fmaf(xp[((size_t)(4 * gq + 0)) << 10], w4.x, acc);
                    acc = fmaf(xp[((size_t)(4 * gq + 1)) << 10], w4.y, acc);
                    acc = fmaf(xp[((size_t)(4 * gq + 2)) << 10], w4.z, acc);
                    acc = fmaf(xp[((size_t)(4 * gq + 3)) << 10], w4.w, acc);
                }
                float ex = acc - g_wsq[k];
                if (ex > bestv) { bestv = ex; besti = k; }
            }
        }
    }

    // output: gather codebook row, write NCHW (warp lanes = consecutive hw -> coalesced)
    const float4* wrow = (const float4*)(wgt + (size_t)besti * D);
    float* op = out + (((size_t)b * D) << 10) + hw;
    float lsum = 0.f;
    #pragma unroll 4
    for (int gq = 0; gq < 64; ++gq) {
        float4 qv = __ldg(wrow + gq);
        float x0 = xp[((size_t)(4 * gq + 0)) << 10];
        float x1 = xp[((size_t)(4 * gq + 1)) << 10];
        float x2 = xp[((size_t)(4 * gq + 2)) << 10];
        float x3 = xp[((size_t)(4 * gq + 3)) << 10];
        float d0 = qv.x - x0, d1 = qv.y - x1, d2 = qv.z - x2, d3 = qv.w - x3;
        lsum = fmaf(d0, d0, lsum); lsum = fmaf(d1, d1, lsum);
        lsum = fmaf(d2, d2, lsum); lsum = fmaf(d3, d3, lsum);
        op[((size_t)(4 * gq + 0)) << 10] = qv.x;
        op[((size_t)(4 * gq + 1)) << 10] = qv.y;
        op[((size_t)(4 * gq + 2)) << 10] = qv.z;
        op[((size_t)(4 * gq + 3)) << 10] = qv.w;
    }
    sred[tid] = lsum;
    __syncthreads();
    #pragma unroll
    for (int s = 64; s > 0; s >>= 1) {
        if (tid < s) sred[tid] += sred[tid + s];
        __syncthreads();
    }
    if (tid == 0) g_partial[blockIdx.x] = sred[0];

    // last-block loss finalize (deterministic; counter self-resets)
    if (tid == 0) {
        __threadfence();
        int c = atomicAdd(&g_count, 1);
        sflg[0] = (c == NBLOCKS - 1) ? 1 : 0;
    }
    __syncthreads();
    if (sflg[0]) {
        __threadfence();
        sred[tid] = g_partial[tid] + g_partial[tid + 128];
        __syncthreads();
        #pragma unroll
        for (int s = 64; s > 0; s >>= 1) {
            if (tid < s) sred[tid] += sred[tid + s];
            __syncthreads();
        }
        if (tid == 0) {
            out[loss_index] = 1.25f * sred[0] / (float)OUT_ELEMS;
            g_count = 0;
        }
    }
}

extern "C" void kernel_launch(void* const* d_in, const int* in_sizes, int n_in,
                              void* d_out, int out_size)
{
    (void)in_sizes; (void)n_in;
    const float* inp = (const float*)d_in[0];   // [32,256,32,32] fp32 NCHW
    const float* wgt = (const float*)d_in[1];   // [1024,256] fp32
    float* out = (float*)d_out;

    (void)cudaFuncSetAttribute(vq_score, cudaFuncAttributeMaxDynamicSharedMemorySize,
                               SMEM_A);

    vq_prep  <<<K / 8, 256>>>(wgt);
    vq_score <<<NBLOCKS, NTHREADS, SMEM_A>>>(inp);
    vq_select<<<NBLOCKS, 128>>>(inp, wgt, out, out_size - 1);
}

// round 10
// speedup vs baseline: 1.7858x; 1.7858x over previous
#include <cuda_runtime.h>
#include <cuda_fp16.h>
#include <cstdint>
#include <cstddef>

#define D         256
#define K         1024
#define TP        128
#define NTHREADS  512
#define NBLOCKS   256
#define OUT_ELEMS 8388608
#define XROW      264            // X smem row (halfs): 528B
#define WROWH     72             // W smem row (halfs): 144B
#define EPSILON   1.0f
#define QCAP      4096

// ---- vq_score smem byte layout ----
#define OFF_XH    0              // 128*264*2 = 67584
#define OFF_WH0   67584          // 18432
#define OFF_WH1   86016          // 18432
#define OFF_WSQ   104448         // 1024 f32
#define OFF_STAGE 108544         // stage: 128 rows(nl) x 136 halfs = 34816
#define SMEM_A    143360
#define OFF_TBUF  OFF_WH0        // 32x132 f32 transpose buffer (X-fill phase only)
#define STAGE_ROW 136            // halfs per nl row (272B, 16B-multiple)

__device__ float          g_wsq[K];
__device__ unsigned short g_whi[K * D];
__device__ unsigned short g_scores[(size_t)K * 32768];  // [k][pos], 64MB
__device__ float          g_smax[32768];
__device__ float          g_partial[NBLOCKS];
__device__ int            g_count;

__device__ __forceinline__ uint32_t smem_u32(const void* p) {
    uint32_t a;
    asm("{ .reg .u64 t; cvta.to.shared.u64 t, %1; cvt.u32.u64 %0, t; }" : "=r"(a) : "l"(p));
    return a;
}
__device__ __forceinline__ void ldsm4(uint32_t* r, uint32_t addr) {
    asm volatile("ldmatrix.sync.aligned.m8n8.x4.shared.b16 {%0,%1,%2,%3}, [%4];"
                 : "=r"(r[0]), "=r"(r[1]), "=r"(r[2]), "=r"(r[3]) : "r"(addr));
}
__device__ __forceinline__ void mma16816(float* c, const uint32_t* a, const uint32_t* b) {
    asm volatile(
        "mma.sync.aligned.m16n8k16.row.col.f32.f16.f16.f32 "
        "{%0,%1,%2,%3}, {%4,%5,%6,%7}, {%8,%9}, {%0,%1,%2,%3};"
        : "+f"(c[0]), "+f"(c[1]), "+f"(c[2]), "+f"(c[3])
        : "r"(a[0]), "r"(a[1]), "r"(a[2]), "r"(a[3]), "r"(b[0]), "r"(b[1]));
}

// ---- prep: 0.5*||w||^2 + fp16 hi of W (warp per row) ----
__global__ void vq_prep(const float* __restrict__ wgt)
{
    int wid  = threadIdx.x >> 5;
    int lane = threadIdx.x & 31;
    int row  = blockIdx.x * 8 + wid;
    const float4* r = (const float4*)(wgt + (size_t)row * D);
    float4 a = r[lane];
    float4 b = r[lane + 32];
    float s = a.x * a.x;
    s = fmaf(a.y, a.y, s); s = fmaf(a.z, a.z, s); s = fmaf(a.w, a.w, s);
    s = fmaf(b.x, b.x, s); s = fmaf(b.y, b.y, s);
    s = fmaf(b.z, b.z, s); s = fmaf(b.w, b.w, s);
    #pragma unroll
    for (int o = 16; o > 0; o >>= 1) s += __shfl_xor_sync(0xffffffffu, s, o);
    if (lane == 0) g_wsq[row] = 0.5f * s;

    float v[2][4] = {{a.x, a.y, a.z, a.w}, {b.x, b.y, b.z, b.w}};
    #pragma unroll
    for (int h = 0; h < 2; ++h) {
        unsigned short ph[4];
        #pragma unroll
        for (int i = 0; i < 4; ++i)
            ph[i] = __half_as_ushort(__float2half_rn(v[h][i]));
        *(uint2*)(g_whi + (size_t)row * D + h * 128 + lane * 4) = *(uint2*)ph;
    }
}

// ---- kernel A: hi-only fp16 GEMM -> fp16 scores [k][pos] + per-pos approx max ----
__global__ void __launch_bounds__(NTHREADS, 1)
vq_score(const float* __restrict__ inp)
{
    extern __shared__ char smem[];
    const uint32_t sb = smem_u32(smem);
    float* wsq_s = (float*)(smem + OFF_WSQ);
    float* tbuf  = (float*)(smem + OFF_TBUF);
    unsigned short* Xh    = (unsigned short*)(smem + OFF_XH);
    unsigned short* stage = (unsigned short*)(smem + OFF_STAGE);   // [nl][p]

    const int tid  = threadIdx.x;
    const int lane = tid & 31;
    const int warp = tid >> 5;
    const int g    = lane >> 2;
    const int t    = lane & 3;
    const int wN   = warp & 3;
    const int wM   = warp >> 2;
    const int mi   = lane >> 3;
    const int mr   = lane & 7;

    const int n0  = blockIdx.x * TP;
    const int b   = n0 >> 10;
    const int hw0 = n0 & 1023;
    const float* xin = inp + (((size_t)b * D) << 10) + hw0;

    wsq_s[tid]       = g_wsq[tid];
    wsq_s[tid + 512] = g_wsq[tid + 512];

    uint32_t aXh[2], rB[2];
    #pragma unroll
    for (int mt = 0; mt < 2; ++mt)
        aXh[mt] = sb + OFF_XH +
            (uint32_t)((wM * 32 + mt * 16 + (mi & 1) * 8 + mr) * XROW + (mi >> 1) * 8) * 2;
    #pragma unroll
    for (int q = 0; q < 2; ++q)
        rB[q] = (uint32_t)((wN * 32 + (q * 2 + (mi >> 1)) * 8 + mr) * WROWH + (mi & 1) * 8) * 2;

    uint4 fh[2];
    #pragma unroll
    for (int j = 0; j < 2; ++j) {
        int idx = tid + j * NTHREADS;
        int code = idx >> 3, seg = idx & 7;
        fh[j] = *(const uint4*)(g_whi + (size_t)code * D + seg * 8);
    }

    // X transpose + fp16 hi (8 slices of 32 dims)
    for (int dc = 0; dc < 8; ++dc) {
        {
            int d  = tid >> 4;
            int p0 = (tid & 15) << 3;
            const float* src = xin + (((size_t)(dc * 32 + d)) << 10) + p0;
            float4 v0 = *(const float4*)(src);
            float4 v1 = *(const float4*)(src + 4);
            float* dst = tbuf + d * 132 + p0;
            dst[0]=v0.x; dst[1]=v0.y; dst[2]=v0.z; dst[3]=v0.w;
            dst[4]=v1.x; dst[5]=v1.y; dst[6]=v1.z; dst[7]=v1.w;
        }
        __syncthreads();
        {
            int p  = tid & 127;
            int dq = tid >> 7;
            uint32_t ph[4];
            #pragma unroll
            for (int i = 0; i < 4; ++i) {
                __half h0 = __float2half_rn(tbuf[(dq * 8 + 2 * i    ) * 132 + p]);
                __half h1 = __float2half_rn(tbuf[(dq * 8 + 2 * i + 1) * 132 + p]);
                ph[i] = (uint32_t)__half_as_ushort(h0) | ((uint32_t)__half_as_ushort(h1) << 16);
            }
            *(uint4*)(Xh + p * XROW + dc * 32 + dq * 8) = make_uint4(ph[0], ph[1], ph[2], ph[3]);
        }
        __syncthreads();
    }

    float acc[2][4][4];
    #pragma unroll
    for (int mt = 0; mt < 2; ++mt)
        #pragma unroll
        for (int nt = 0; nt < 4; ++nt)
            #pragma unroll
            for (int j = 0; j < 4; ++j) acc[mt][nt][j] = 0.f;
    float bestv[4] = {-1e30f, -1e30f, -1e30f, -1e30f};

    for (int piece = 0; piece < 32; ++piece) {
        const int nc   = piece >> 2;
        const int kc   = piece & 3;
        const int bsel = piece & 1;
        unsigned short* WhB = (unsigned short*)(smem + (bsel ? OFF_WH1 : OFF_WH0));

        #pragma unroll
        for (int j = 0; j < 2; ++j) {
            int idx = tid + j * NTHREADS;
            int code = idx >> 3, seg = idx & 7;
            *(uint4*)(WhB + code * WROWH + seg * 8) = fh[j];
        }
        if (piece + 1 < 32) {
            int nn = (piece + 1) >> 2, nk = (piece + 1) & 3;
            #pragma unroll
            for (int j = 0; j < 2; ++j) {
                int idx = tid + j * NTHREADS;
                int code = idx >> 3, seg = idx & 7;
                fh[j] = *(const uint4*)(g_whi + (size_t)(nn * 128 + code) * D + nk * 64 + seg * 8);
            }
        }
        __syncthreads();

        const uint32_t wbh = sb + (bsel ? OFF_WH1 : OFF_WH0);
        const uint32_t ao0 = (uint32_t)kc * 128;
        #pragma unroll
        for (int ks = 0; ks < 4; ++ks) {
            uint32_t ah0[4], ah1[4], bh[8];
            uint32_t ao = ao0 + ks * 32;
            ldsm4(ah0, aXh[0] + ao);
            ldsm4(ah1, aXh[1] + ao);
            ldsm4(bh + 0, wbh + rB[0] + ks * 32);
            ldsm4(bh + 4, wbh + rB[1] + ks * 32);
            #pragma unroll
            for (int nt = 0; nt < 4; ++nt) {
                mma16816(acc[0][nt], ah0, &bh[nt * 2]);
                mma16816(acc[1][nt], ah1, &bh[nt * 2]);
            }
        }

        if (kc == 3) {
            // fold: s = acc - 0.5||w||^2 -> approx max + fp16 stage [nl][p]
            #pragma unroll
            for (int mt = 0; mt < 2; ++mt)
                #pragma unroll
                for (int nt = 0; nt < 4; ++nt)
                    #pragma unroll
                    for (int j = 0; j < 4; ++j) {
                        int nl = wN * 32 + nt * 8 + 2 * t + (j & 1);
                        int p  = wM * 32 + mt * 16 + (j >> 1) * 8 + g;
                        float s = acc[mt][nt][j] - wsq_s[nc * 128 + nl];
                        int slot = mt * 2 + (j >> 1);
                        bestv[slot] = fmaxf(bestv[slot], s);
                        stage[nl * STAGE_ROW + p] = __half_as_ushort(__float2half_rn(s));
                        acc[mt][nt][j] = 0.f;
                    }
            __syncthreads();
            // copy stage -> g_scores[k][pos] (coalesced: row nl over positions)
            #pragma unroll
            for (int j2 = 0; j2 < 4; ++j2) {
                int idx = tid + j2 * NTHREADS;      // 0..2047 = nl*16 + seg
                int nl  = idx >> 4, seg = idx & 15;
                uint4 v = *(const uint4*)(stage + nl * STAGE_ROW + seg * 8);
                *(uint4*)(g_scores + (size_t)(nc * 128 + nl) * 32768 + n0 + seg * 8) = v;
            }
            __syncthreads();
        }
    }

    // approx max reduction -> g_smax (reuse stage region)
    #pragma unroll
    for (int o = 1; o <= 2; o <<= 1)
        #pragma unroll
        for (int s = 0; s < 4; ++s)
            bestv[s] = fmaxf(bestv[s], __shfl_xor_sync(0xffffffffu, bestv[s], o));
    float* redv = (float*)(smem + OFF_STAGE);
    if (t == 0) {
        #pragma unroll
        for (int s = 0; s < 4; ++s) {
            int p = wM * 32 + (s >> 1) * 16 + (s & 1) * 8 + g;
            redv[p * 4 + wN] = bestv[s];
        }
    }
    __syncthreads();
    if (tid < TP) {
        float m = fmaxf(fmaxf(redv[tid * 4], redv[tid * 4 + 1]),
                        fmaxf(redv[tid * 4 + 2], redv[tid * 4 + 3]));
        g_smax[n0 + tid] = m;
    }
}

// ---- kernel B: coalesced scan + warp-cooperative exact rescue + output + loss ----
__global__ void __launch_bounds__(256, 4)
vq_select(const float* __restrict__ inp, const float* __restrict__ wgt,
          float* __restrict__ out, int loss_index)
{
    __shared__ int   qpk[QCAP];
    __shared__ float qval[QCAP];
    __shared__ int   sidx[TP];
    __shared__ float sred[256];
    __shared__ int   qn, sflg;

    const int tid  = threadIdx.x;
    const int lane = tid & 31;
    const int warp = tid >> 5;
    const int p    = tid & 127;          // local position
    const int kh   = tid >> 7;           // k-half 0/1

    const int n0  = blockIdx.x * TP;
    const int b   = n0 >> 10;
    const int hw0 = n0 & 1023;
    const int q   = n0 + p;              // global position
    const float* xin = inp + (((size_t)b * D) << 10) + hw0;

    if (tid == 0) qn = 0;
    __syncthreads();

    // scan this position's k-half for candidates >= smax - EPS (coalesced over p)
    {
        const float thr = __ldg(&g_smax[q]) - EPSILON;
        const unsigned short* srow = g_scores + (size_t)(kh * 512) * 32768 + q;
        #pragma unroll 1
        for (int kk = 0; kk < 512; kk += 8) {
            float s[8];
            #pragma unroll
            for (int u = 0; u < 8; ++u)
                s[u] = __half2float(__ushort_as_half(
                    __ldg(srow + (size_t)(kk + u) * 32768)));
            #pragma unroll
            for (int u = 0; u < 8; ++u) {
                if (s[u] >= thr) {
                    int idx = atomicAdd(&qn, 1);
                    if (idx < QCAP) qpk[idx] = (p << 16) | (kh * 512 + kk + u);
                }
            }
        }
    }
    __syncthreads();
    const int nq = (qn < QCAP) ? qn : QCAP;

    // warp-cooperative exact fp32 score per candidate (lane covers dims lane+32m)
    for (int ci = warp; ci < nq; ci += 8) {
        int pk = qpk[ci];
        int cp = pk >> 16, ck = pk & 1023;
        const float* wr = wgt + (size_t)ck * D;
        const float* xr = xin + cp;
        float a = 0.f;
        #pragma unroll
        for (int m = 0; m < 8; ++m) {
            int d = lane + 32 * m;
            a = fmaf(__ldg(xr + (((size_t)d) << 10)), __ldg(wr + d), a);
        }
        #pragma unroll
        for (int o = 16; o > 0; o >>= 1) a += __shfl_xor_sync(0xffffffffu, a, o);
        if (lane == 0) qval[ci] = a - __ldg(&g_wsq[ck]);
    }
    __syncthreads();

    // per-position exact argmax over its candidates (order-independent compare)
    if (tid < TP) {
        float bv = -1e30f;
        int   bk = 0;
        for (int i = 0; i < nq; ++i) {
            int pk = qpk[i];
            if ((pk >> 16) == tid) {
                float v = qval[i];
                int   k = pk & 1023;
                if (v > bv || (v == bv && k < bk)) { bv = v; bk = k; }
            }
        }
        sidx[tid] = bk;
    }
    __syncthreads();

    // output: gather codebook row, write NCHW, loss partial
    {
        int ds = kh;                      // split 64 float4-groups in 2 halves
        int myidx = sidx[p];
        const float4* wrow = (const float4*)(wgt + (size_t)myidx * D);
        float* op = out + (((size_t)b * D) << 10) + hw0 + p;
        const float* xp = xin + p;
        float lsum = 0.f;
        #pragma unroll 4
        for (int i = 0; i < 32; ++i) {
            int gq = ds + (i << 1);
            float4 qv = __ldg(wrow + gq);
            float x0 = xp[((size_t)(4 * gq + 0)) << 10];
            float x1 = xp[((size_t)(4 * gq + 1)) << 10];
            float x2 = xp[((size_t)(4 * gq + 2)) << 10];
            float x3 = xp[((size_t)(4 * gq + 3)) << 10];
            float d0 = qv.x - x0, d1 = qv.y - x1, d2 = qv.z - x2, d3 = qv.w - x3;
            lsum = fmaf(d0, d0, lsum); lsum = fmaf(d1, d1, lsum);
            lsum = fmaf(d2, d2, lsum); lsum = fmaf(d3, d3, lsum);
            op[((size_t)(4 * gq + 0)) << 10] = qv.x;
            op[((size_t)(4 * gq + 1)) << 10] = qv.y;
            op[((size_t)(4 * gq + 2)) << 10] = qv.z;
            op[((size_t)(4 * gq + 3)) << 10] = qv.w;
        }
        sred[tid] = lsum;
    }
    __syncthreads();
    #pragma unroll
    for (int s = 128; s > 0; s >>= 1) {
        if (tid < s) sred[tid] += sred[tid + s];
        __syncthreads();
    }
    if (tid == 0) g_partial[blockIdx.x] = sred[0];

    // last-block loss finalize (deterministic; counter self-resets)
    if (tid == 0) {
        __threadfence();
        int c = atomicAdd(&g_count, 1);
        sflg = (c == NBLOCKS - 1) ? 1 : 0;
    }
    __syncthreads();
    if (sflg) {
        __threadfence();
        sred[tid] = g_partial[tid];       // NBLOCKS == 256 == blockDim
        __syncthreads();
        #pragma unroll
        for (int s = 128; s > 0; s >>= 1) {
            if (tid < s) sred[tid] += sred[tid + s];
            __syncthreads();
        }
        if (tid == 0) {
            out[loss_index] = 1.25f * sred[0] / (float)OUT_ELEMS;
            g_count = 0;
        }
    }
}

extern "C" void kernel_launch(void* const* d_in, const int* in_sizes, int n_in,
                              void* d_out, int out_size)
{
    (void)in_sizes; (void)n_in;
    const float* inp = (const float*)d_in[0];   // [32,256,32,32] fp32 NCHW
    const float* wgt = (const float*)d_in[1];   // [1024,256] fp32
    float* out = (float*)d_out;

    (void)cudaFuncSetAttribute(vq_score, cudaFuncAttributeMaxDynamicSharedMemorySize,
                               SMEM_A);

    vq_prep  <<<K / 8, 256>>>(wgt);
    vq_score <<<NBLOCKS, NTHREADS, SMEM_A>>>(inp);
    vq_select<<<NBLOCKS, 256>>>(inp, wgt, out, out_size - 1);
}

// round 11
// speedup vs baseline: 2.0945x; 1.1729x over previous
#include <cuda_runtime.h>
#include <cuda_fp16.h>
#include <cstdint>
#include <cstddef>

#define D         256
#define K         1024
#define TP        128
#define NTHREADS  512
#define NBLOCKS   256
#define OUT_ELEMS 8388608
#define XROW      264            // X smem row (halfs): 528B
#define WROWH     72             // W smem row (halfs): 144B
#define EPSILON   1.0f
#define QCAP      2048
#define STAGE_ROW 136

// ---- smem byte layout ----
#define OFF_XH    0              // 67584
#define OFF_XL    67584          // 67584
#define OFF_WH0   135168         // 18432
#define OFF_WH1   153600         // 18432
#define OFF_WSQ   172032         // 4096
#define OFF_STAGE 176128         // 34816 (stage; later aliased by queue/reduce)
#define SMEM_A    210944
#define OFF_TBUF  OFF_WH0        // 32x132 f32 transpose buffer (X-fill phase only)
// aliases inside STAGE (used only after mainloop):
#define OFF_QPK   (OFF_STAGE)            // 2048 i32
#define OFF_QVAL  (OFF_STAGE + 8192)     // 2048 f32
#define OFF_REDV  (OFF_STAGE + 16384)    // 128*4 f32
#define OFF_MAXV  (OFF_STAGE + 18432)    // 128 f32
#define OFF_SIDX  (OFF_STAGE + 18944)    // 128 i32
#define OFF_SRED  (OFF_STAGE + 19456)    // 512 f32
#define OFF_CTL   (OFF_STAGE + 21504)    // qn, sflg

__device__ float          g_wsq[K];
__device__ unsigned short g_whi[K * D];
__device__ unsigned short g_sc[(size_t)NBLOCKS * K * TP];   // [blk][k][p] fp16, 64MB
__device__ float          g_partial[NBLOCKS];
__device__ int            g_count;

__device__ __forceinline__ uint32_t smem_u32(const void* p) {
    uint32_t a;
    asm("{ .reg .u64 t; cvta.to.shared.u64 t, %1; cvt.u32.u64 %0, t; }" : "=r"(a) : "l"(p));
    return a;
}
__device__ __forceinline__ void ldsm4(uint32_t* r, uint32_t addr) {
    asm volatile("ldmatrix.sync.aligned.m8n8.x4.shared.b16 {%0,%1,%2,%3}, [%4];"
                 : "=r"(r[0]), "=r"(r[1]), "=r"(r[2]), "=r"(r[3]) : "r"(addr));
}
__device__ __forceinline__ void mma16816(float* c, const uint32_t* a, const uint32_t* b) {
    asm volatile(
        "mma.sync.aligned.m16n8k16.row.col.f32.f16.f16.f32 "
        "{%0,%1,%2,%3}, {%4,%5,%6,%7}, {%8,%9}, {%0,%1,%2,%3};"
        : "+f"(c[0]), "+f"(c[1]), "+f"(c[2]), "+f"(c[3])
        : "r"(a[0]), "r"(a[1]), "r"(a[2]), "r"(a[3]), "r"(b[0]), "r"(b[1]));
}

// ---- prep: 0.5*||w||^2 + fp16 hi of W (warp per row) ----
__global__ void vq_prep(const float* __restrict__ wgt)
{
    int wid  = threadIdx.x >> 5;
    int lane = threadIdx.x & 31;
    int row  = blockIdx.x * 8 + wid;
    const float4* r = (const float4*)(wgt + (size_t)row * D);
    float4 a = r[lane];
    float4 b = r[lane + 32];
    float s = a.x * a.x;
    s = fmaf(a.y, a.y, s); s = fmaf(a.z, a.z, s); s = fmaf(a.w, a.w, s);
    s = fmaf(b.x, b.x, s); s = fmaf(b.y, b.y, s);
    s = fmaf(b.z, b.z, s); s = fmaf(b.w, b.w, s);
    #pragma unroll
    for (int o = 16; o > 0; o >>= 1) s += __shfl_xor_sync(0xffffffffu, s, o);
    if (lane == 0) g_wsq[row] = 0.5f * s;

    float v[2][4] = {{a.x, a.y, a.z, a.w}, {b.x, b.y, b.z, b.w}};
    #pragma unroll
    for (int h = 0; h < 2; ++h) {
        unsigned short ph[4];
        #pragma unroll
        for (int i = 0; i < 4; ++i)
            ph[i] = __half_as_ushort(__float2half_rn(v[h][i]));
        *(uint2*)(g_whi + (size_t)row * D + h * 128 + lane * 4) = *(uint2*)ph;
    }
}

// ---- fused main: hi-only GEMM + spill + in-CTA scan + exact rescue + output ----
__global__ void __launch_bounds__(NTHREADS, 1)
vq_main(const float* __restrict__ inp, const float* __restrict__ wgt,
        float* __restrict__ out, int loss_index)
{
    extern __shared__ char smem[];
    const uint32_t sb = smem_u32(smem);
    float* wsq_s = (float*)(smem + OFF_WSQ);
    float* tbuf  = (float*)(smem + OFF_TBUF);
    unsigned short* Xh    = (unsigned short*)(smem + OFF_XH);
    unsigned short* Xl    = (unsigned short*)(smem + OFF_XL);
    unsigned short* stage = (unsigned short*)(smem + OFF_STAGE);

    const int tid  = threadIdx.x;
    const int lane = tid & 31;
    const int warp = tid >> 5;
    const int g    = lane >> 2;
    const int t    = lane & 3;
    const int wN   = warp & 3;
    const int wM   = warp >> 2;
    const int mi   = lane >> 3;
    const int mr   = lane & 7;

    const int n0  = blockIdx.x * TP;
    const int b   = n0 >> 10;
    const int hw0 = n0 & 1023;
    const float* xin = inp + (((size_t)b * D) << 10) + hw0;

    wsq_s[tid]       = g_wsq[tid];
    wsq_s[tid + 512] = g_wsq[tid + 512];

    uint32_t aXh[2], rB[2];
    #pragma unroll
    for (int mt = 0; mt < 2; ++mt)
        aXh[mt] = sb + OFF_XH +
            (uint32_t)((wM * 32 + mt * 16 + (mi & 1) * 8 + mr) * XROW + (mi >> 1) * 8) * 2;
    #pragma unroll
    for (int q = 0; q < 2; ++q)
        rB[q] = (uint32_t)((wN * 32 + (q * 2 + (mi >> 1)) * 8 + mr) * WROWH + (mi & 1) * 8) * 2;

    uint4 fh[2];
    #pragma unroll
    for (int j = 0; j < 2; ++j) {
        int idx = tid + j * NTHREADS;
        int code = idx >> 3, seg = idx & 7;
        fh[j] = *(const uint4*)(g_whi + (size_t)code * D + seg * 8);
    }

    // ---- X transpose + fp16 hi/lo split (8 slices of 32 dims) ----
    for (int dc = 0; dc < 8; ++dc) {
        {
            int d  = tid >> 4;
            int p0 = (tid & 15) << 3;
            const float* src = xin + (((size_t)(dc * 32 + d)) << 10) + p0;
            float4 v0 = *(const float4*)(src);
            float4 v1 = *(const float4*)(src + 4);
            float* dst = tbuf + d * 132 + p0;
            dst[0]=v0.x; dst[1]=v0.y; dst[2]=v0.z; dst[3]=v0.w;
            dst[4]=v1.x; dst[5]=v1.y; dst[6]=v1.z; dst[7]=v1.w;
        }
        __syncthreads();
        {
            int p  = tid & 127;
            int dq = tid >> 7;
            uint32_t ph[4], pl[4];
            #pragma unroll
            for (int i = 0; i < 4; ++i) {
                float x0 = tbuf[(dq * 8 + 2 * i    ) * 132 + p];
                float x1 = tbuf[(dq * 8 + 2 * i + 1) * 132 + p];
                __half h0 = __float2half_rn(x0), h1 = __float2half_rn(x1);
                __half l0 = __float2half_rn(x0 - __half2float(h0));
                __half l1 = __float2half_rn(x1 - __half2float(h1));
                ph[i] = (uint32_t)__half_as_ushort(h0) | ((uint32_t)__half_as_ushort(h1) << 16);
                pl[i] = (uint32_t)__half_as_ushort(l0) | ((uint32_t)__half_as_ushort(l1) << 16);
            }
            int ho = p * XROW + dc * 32 + dq * 8;
            *(uint4*)(Xh + ho) = make_uint4(ph[0], ph[1], ph[2], ph[3]);
            *(uint4*)(Xl + ho) = make_uint4(pl[0], pl[1], pl[2], pl[3]);
        }
        __syncthreads();
    }

    float acc[2][4][4];
    #pragma unroll
    for (int mt = 0; mt < 2; ++mt)
        #pragma unroll
        for (int nt = 0; nt < 4; ++nt)
            #pragma unroll
            for (int j = 0; j < 4; ++j) acc[mt][nt][j] = 0.f;
    float bestv[4] = {-1e30f, -1e30f, -1e30f, -1e30f};

    // ---- main loop: 32 pieces (8 nc x 4 kc), hi-only MMAs ----
    for (int piece = 0; piece < 32; ++piece) {
        const int nc   = piece >> 2;
        const int kc   = piece & 3;
        const int bsel = piece & 1;
        unsigned short* WhB = (unsigned short*)(smem + (bsel ? OFF_WH1 : OFF_WH0));

        #pragma unroll
        for (int j = 0; j < 2; ++j) {
            int idx = tid + j * NTHREADS;
            int code = idx >> 3, seg = idx & 7;
            *(uint4*)(WhB + code * WROWH + seg * 8) = fh[j];
        }
        if (piece + 1 < 32) {
            int nn = (piece + 1) >> 2, nk = (piece + 1) & 3;
            #pragma unroll
            for (int j = 0; j < 2; ++j) {
                int idx = tid + j * NTHREADS;
                int code = idx >> 3, seg = idx & 7;
                fh[j] = *(const uint4*)(g_whi + (size_t)(nn * 128 + code) * D + nk * 64 + seg * 8);
            }
        }
        __syncthreads();

        const uint32_t wbh = sb + (bsel ? OFF_WH1 : OFF_WH0);
        const uint32_t ao0 = (uint32_t)kc * 128;
        #pragma unroll
        for (int ks = 0; ks < 4; ++ks) {
            uint32_t ah0[4], ah1[4], bh[8];
            uint32_t ao = ao0 + ks * 32;
            ldsm4(ah0, aXh[0] + ao);
            ldsm4(ah1, aXh[1] + ao);
            ldsm4(bh + 0, wbh + rB[0] + ks * 32);
            ldsm4(bh + 4, wbh + rB[1] + ks * 32);
            #pragma unroll
            for (int nt = 0; nt < 4; ++nt) {
                mma16816(acc[0][nt], ah0, &bh[nt * 2]);
                mma16816(acc[1][nt], ah1, &bh[nt * 2]);
            }
        }

        if (kc == 3) {
            // fold: s = acc - 0.5||w||^2 -> slot max + fp16 stage [nl][p]
            #pragma unroll
            for (int mt = 0; mt < 2; ++mt)
                #pragma unroll
                for (int nt = 0; nt < 4; ++nt)
                    #pragma unroll
                    for (int j = 0; j < 4; ++j) {
                        int nl = wN * 32 + nt * 8 + 2 * t + (j & 1);
                        int p  = wM * 32 + mt * 16 + (j >> 1) * 8 + g;
                        float s = acc[mt][nt][j] - wsq_s[nc * 128 + nl];
                        int slot = mt * 2 + (j >> 1);
                        bestv[slot] = fmaxf(bestv[slot], s);
                        stage[nl * STAGE_ROW + p] = __half_as_ushort(__float2half_rn(s));
                        acc[mt][nt][j] = 0.f;
                    }
            __syncthreads();
            // spill stage -> g_sc[blk][k][p] (coalesced uint4)
            #pragma unroll
            for (int j2 = 0; j2 < 4; ++j2) {
                int idx = tid + j2 * NTHREADS;      // 0..2047 = nl*16 + seg
                int nl  = idx >> 4, seg = idx & 15;
                uint4 v = *(const uint4*)(stage + nl * STAGE_ROW + seg * 8);
                *(uint4*)(g_sc + ((size_t)blockIdx.x << 17)
                               + ((size_t)(nc * 128 + nl) << 7) + seg * 8) = v;
            }
            __syncthreads();
        }
    }

    // ---- final approx max per position ----
    #pragma unroll
    for (int o = 1; o <= 2; o <<= 1)
        #pragma unroll
        for (int s = 0; s < 4; ++s)
            bestv[s] = fmaxf(bestv[s], __shfl_xor_sync(0xffffffffu, bestv[s], o));
    __threadfence_block();
    __syncthreads();                          // stage free; alias region live now
    float* redv = (float*)(smem + OFF_REDV);
    float* maxv = (float*)(smem + OFF_MAXV);
    int*   qpk  = (int*)(smem + OFF_QPK);
    float* qval = (float*)(smem + OFF_QVAL);
    int*   sidx = (int*)(smem + OFF_SIDX);
    float* sred = (float*)(smem + OFF_SRED);
    int*   ctl  = (int*)(smem + OFF_CTL);     // [0]=qn, [1]=sflg
    if (t == 0) {
        #pragma unroll
        for (int s = 0; s < 4; ++s) {
            int p = wM * 32 + (s >> 1) * 16 + (s & 1) * 8 + g;
            redv[p * 4 + wN] = bestv[s];
        }
    }
    if (tid == 0) ctl[0] = 0;
    __syncthreads();
    if (tid < TP)
        maxv[tid] = fmaxf(fmaxf(redv[tid * 4], redv[tid * 4 + 1]),
                          fmaxf(redv[tid * 4 + 2], redv[tid * 4 + 3]));
    __syncthreads();

    // ---- scan own score block (L2-hot) for candidates >= max - EPS ----
    {
        const int p  = tid & 127;
        const int kq = tid >> 7;              // quarter: 256 codes
        const float thr = maxv[p] - EPSILON;
        const unsigned short* srow = g_sc + ((size_t)blockIdx.x << 17)
                                          + ((size_t)(kq * 256) << 7) + p;
        #pragma unroll 1
        for (int kk = 0; kk < 256; kk += 8) {
            float s[8];
            #pragma unroll
            for (int u = 0; u < 8; ++u)
                s[u] = __half2float(__ushort_as_half(srow[(size_t)(kk + u) << 7]));
            #pragma unroll
            for (int u = 0; u < 8; ++u) {
                if (s[u] >= thr) {
                    int idx = atomicAdd(&ctl[0], 1);
                    if (idx < QCAP) qpk[idx] = (p << 16) | (kq * 256 + kk + u);
                }
            }
        }
    }
    __syncthreads();
    const int nq = (ctl[0] < QCAP) ? ctl[0] : QCAP;

    // ---- warp-cooperative exact rescue: x = xh+xl (2^-22), w fp32 ----
    for (int ci = warp; ci < nq; ci += 16) {
        int pk = qpk[ci];
        int cp = pk >> 16, ck = pk & 1023;
        const float* wr = wgt + (size_t)ck * D;
        float a = 0.f;
        #pragma unroll
        for (int m = 0; m < 8; ++m) {
            int d = lane + 32 * m;
            float xf = __half2float(__ushort_as_half(Xh[cp * XROW + d]))
                     + __half2float(__ushort_as_half(Xl[cp * XROW + d]));
            a = fmaf(xf, wr[d], a);
        }
        #pragma unroll
        for (int o = 16; o > 0; o >>= 1) a += __shfl_xor_sync(0xffffffffu, a, o);
        if (lane == 0) qval[ci] = a - wsq_s[ck];
    }
    __syncthreads();

    // ---- per-position exact argmax over candidates (order-independent) ----
    if (tid < TP) {
        float bv = -1e30f;
        int   bk = 0;
        for (int i = 0; i < nq; ++i) {
            int pk = qpk[i];
            if ((pk >> 16) == tid) {
                float v = qval[i];
                int   k = pk & 1023;
                if (v > bv || (v == bv && k < bk)) { bv = v; bk = k; }
            }
        }
        sidx[tid] = bk;
    }
    __syncthreads();

    // ---- output: gather + NCHW write + loss partial ----
    {
        int p  = tid & 127;
        int ds = tid >> 7;
        int myidx = sidx[p];
        const float4* wrow = (const float4*)(wgt + (size_t)myidx * D);
        float* op = out + (((size_t)b * D) << 10) + hw0 + p;
        const float* xp = xin + p;
        float lsum = 0.f;
        #pragma unroll 4
        for (int i = 0; i < 16; ++i) {
            int gq = ds + (i << 2);
            float4 qv = __ldg(wrow + gq);
            float x0 = xp[((size_t)(4 * gq + 0)) << 10];
            float x1 = xp[((size_t)(4 * gq + 1)) << 10];
            float x2 = xp[((size_t)(4 * gq + 2)) << 10];
            float x3 = xp[((size_t)(4 * gq + 3)) << 10];
            float d0 = qv.x - x0, d1 = qv.y - x1, d2 = qv.z - x2, d3 = qv.w - x3;
            lsum = fmaf(d0, d0, lsum); lsum = fmaf(d1, d1, lsum);
            lsum = fmaf(d2, d2, lsum); lsum = fmaf(d3, d3, lsum);
            op[((size_t)(4 * gq + 0)) << 10] = qv.x;
            op[((size_t)(4 * gq + 1)) << 10] = qv.y;
            op[((size_t)(4 * gq + 2)) << 10] = qv.z;
            op[((size_t)(4 * gq + 3)) << 10] = qv.w;
        }
        sred[tid] = lsum;
    }
    __syncthreads();
    #pragma unroll
    for (int s = NTHREADS / 2; s > 0; s >>= 1) {
        if (tid < s) sred[tid] += sred[tid + s];
        __syncthreads();
    }
    if (tid == 0) g_partial[blockIdx.x] = sred[0];

    // ---- last-block loss finalize (deterministic; counter self-resets) ----
    if (tid == 0) {
        __threadfence();
        int c = atomicAdd(&g_count, 1);
        ctl[1] = (c == NBLOCKS - 1) ? 1 : 0;
    }
    __syncthreads();
    if (ctl[1]) {
        __threadfence();
        sred[tid] = (tid < NBLOCKS) ? g_partial[tid] : 0.f;
        __syncthreads();
        #pragma unroll
        for (int s = NTHREADS / 2; s > 0; s >>= 1) {
            if (tid < s) sred[tid] += sred[tid + s];
            __syncthreads();
        }
        if (tid == 0) {
            out[loss_index] = 1.25f * sred[0] / (float)OUT_ELEMS;
            g_count = 0;
        }
    }
}

extern "C" void kernel_launch(void* const* d_in, const int* in_sizes, int n_in,
                              void* d_out, int out_size)
{
    (void)in_sizes; (void)n_in;
    const float* inp = (const float*)d_in[0];   // [32,256,32,32] fp32 NCHW
    const float* wgt = (const float*)d_in[1];   // [1024,256] fp32
    float* out = (float*)d_out;

    (void)cudaFuncSetAttribute(vq_main, cudaFuncAttributeMaxDynamicSharedMemorySize,
                               SMEM_A);

    vq_prep<<<K / 8, 256>>>(wgt);
    vq_main<<<NBLOCKS, NTHREADS, SMEM_A>>>(inp, wgt, out, out_size - 1);
}

// round 12
// speedup vs baseline: 2.1209x; 1.0126x over previous
#include <cuda_runtime.h>
#include <cuda_fp16.h>
#include <cstdint>
#include <cstddef>

#define D         256
#define K         1024
#define TP        128
#define NTHREADS  512
#define NBLOCKS   256
#define OUT_ELEMS 8388608
#define XROW      264            // X smem row (halfs): 528B
#define WROWH     72             // W smem row (halfs): 144B
#define EPSILON   1.0f
#define QCAP      4096

// ---- smem byte layout ----
#define OFF_XH    0              // 67584
#define OFF_XL    67584          // 67584
#define OFF_WH0   135168         // 18432
#define OFF_WH1   153600         // 18432
#define OFF_WSQ   172032         // 4096
#define OFF_QPK   176128         // 16384 (4096 i32)
#define OFF_QVAL  192512         // 16384 (4096 f32)
#define OFF_REDV  208896         // 128*4 f32
#define OFF_MAXV  210944         // 128 f32
#define OFF_SIDX  211456         // 128 i32
#define OFF_SRED  211968         // 512 f32
#define OFF_CTL   214016         // qn, sflg
#define SMEM_A    214032
#define OFF_TBUF  OFF_WH0        // 32x132 f32 transpose buffer (X-fill phase only)

__device__ float          g_wsq[K];
__device__ unsigned short g_whi[K * D];
__device__ float          g_partial[NBLOCKS];
__device__ int            g_count;

__device__ __forceinline__ uint32_t smem_u32(const void* p) {
    uint32_t a;
    asm("{ .reg .u64 t; cvta.to.shared.u64 t, %1; cvt.u32.u64 %0, t; }" : "=r"(a) : "l"(p));
    return a;
}
__device__ __forceinline__ void ldsm4(uint32_t* r, uint32_t addr) {
    asm volatile("ldmatrix.sync.aligned.m8n8.x4.shared.b16 {%0,%1,%2,%3}, [%4];"
                 : "=r"(r[0]), "=r"(r[1]), "=r"(r[2]), "=r"(r[3]) : "r"(addr));
}
__device__ __forceinline__ void mma16816(float* c, const uint32_t* a, const uint32_t* b) {
    asm volatile(
        "mma.sync.aligned.m16n8k16.row.col.f32.f16.f16.f32 "
        "{%0,%1,%2,%3}, {%4,%5,%6,%7}, {%8,%9}, {%0,%1,%2,%3};"
        : "+f"(c[0]), "+f"(c[1]), "+f"(c[2]), "+f"(c[3])
        : "r"(a[0]), "r"(a[1]), "r"(a[2]), "r"(a[3]), "r"(b[0]), "r"(b[1]));
}

// ---- prep: 0.5*||w||^2 + fp16 hi of W (warp per row) ----
__global__ void vq_prep(const float* __restrict__ wgt)
{
    int wid  = threadIdx.x >> 5;
    int lane = threadIdx.x & 31;
    int row  = blockIdx.x * 8 + wid;
    const float4* r = (const float4*)(wgt + (size_t)row * D);
    float4 a = r[lane];
    float4 b = r[lane + 32];
    float s = a.x * a.x;
    s = fmaf(a.y, a.y, s); s = fmaf(a.z, a.z, s); s = fmaf(a.w, a.w, s);
    s = fmaf(b.x, b.x, s); s = fmaf(b.y, b.y, s);
    s = fmaf(b.z, b.z, s); s = fmaf(b.w, b.w, s);
    #pragma unroll
    for (int o = 16; o > 0; o >>= 1) s += __shfl_xor_sync(0xffffffffu, s, o);
    if (lane == 0) g_wsq[row] = 0.5f * s;

    float v[2][4] = {{a.x, a.y, a.z, a.w}, {b.x, b.y, b.z, b.w}};
    #pragma unroll
    for (int h = 0; h < 2; ++h) {
        unsigned short ph[4];
        #pragma unroll
        for (int i = 0; i < 4; ++i)
            ph[i] = __half_as_ushort(__float2half_rn(v[h][i]));
        *(uint2*)(g_whi + (size_t)row * D + h * 128 + lane * 4) = *(uint2*)ph;
    }
}

// ---- fused main: hi-only GEMM + in-fold candidate queue + exact rescue + output ----
__global__ void __launch_bounds__(NTHREADS, 1)
vq_main(const float* __restrict__ inp, const float* __restrict__ wgt,
        float* __restrict__ out, int loss_index)
{
    extern __shared__ char smem[];
    const uint32_t sb = smem_u32(smem);
    float* wsq_s = (float*)(smem + OFF_WSQ);
    float* tbuf  = (float*)(smem + OFF_TBUF);
    unsigned short* Xh = (unsigned short*)(smem + OFF_XH);
    unsigned short* Xl = (unsigned short*)(smem + OFF_XL);
    int*   qpk  = (int*)(smem + OFF_QPK);
    float* qval = (float*)(smem + OFF_QVAL);
    float* redv = (float*)(smem + OFF_REDV);
    float* maxv = (float*)(smem + OFF_MAXV);
    int*   sidx = (int*)(smem + OFF_SIDX);
    float* sred = (float*)(smem + OFF_SRED);
    int*   ctl  = (int*)(smem + OFF_CTL);     // [0]=qn, [1]=sflg

    const int tid  = threadIdx.x;
    const int lane = tid & 31;
    const int warp = tid >> 5;
    const int g    = lane >> 2;
    const int t    = lane & 3;
    const int wN   = warp & 3;
    const int wM   = warp >> 2;
    const int mi   = lane >> 3;
    const int mr   = lane & 7;

    const int n0  = blockIdx.x * TP;
    const int b   = n0 >> 10;
    const int hw0 = n0 & 1023;
    const float* xin = inp + (((size_t)b * D) << 10) + hw0;

    wsq_s[tid]       = g_wsq[tid];
    wsq_s[tid + 512] = g_wsq[tid + 512];
    if (tid == 0) ctl[0] = 0;
    if (tid < TP) maxv[tid] = -1e30f;

    // positions owned per accumulator slot (independent of t)
    int parr[4];
    #pragma unroll
    for (int s = 0; s < 4; ++s)
        parr[s] = wM * 32 + (s >> 1) * 16 + (s & 1) * 8 + g;

    uint32_t aXh[2], rB[2];
    #pragma unroll
    for (int mt = 0; mt < 2; ++mt)
        aXh[mt] = sb + OFF_XH +
            (uint32_t)((wM * 32 + mt * 16 + (mi & 1) * 8 + mr) * XROW + (mi >> 1) * 8) * 2;
    #pragma unroll
    for (int q = 0; q < 2; ++q)
        rB[q] = (uint32_t)((wN * 32 + (q * 2 + (mi >> 1)) * 8 + mr) * WROWH + (mi & 1) * 8) * 2;

    uint4 fh[2];
    #pragma unroll
    for (int j = 0; j < 2; ++j) {
        int idx = tid + j * NTHREADS;
        int code = idx >> 3, seg = idx & 7;
        fh[j] = *(const uint4*)(g_whi + (size_t)code * D + seg * 8);
    }

    // ---- X transpose + fp16 hi/lo split (8 slices of 32 dims) ----
    for (int dc = 0; dc < 8; ++dc) {
        {
            int d  = tid >> 4;
            int p0 = (tid & 15) << 3;
            const float* src = xin + (((size_t)(dc * 32 + d)) << 10) + p0;
            float4 v0 = *(const float4*)(src);
            float4 v1 = *(const float4*)(src + 4);
            float* dst = tbuf + d * 132 + p0;
            dst[0]=v0.x; dst[1]=v0.y; dst[2]=v0.z; dst[3]=v0.w;
            dst[4]=v1.x; dst[5]=v1.y; dst[6]=v1.z; dst[7]=v1.w;
        }
        __syncthreads();
        {
            int p  = tid & 127;
            int dq = tid >> 7;
            uint32_t ph[4], pl[4];
            #pragma unroll
            for (int i = 0; i < 4; ++i) {
                float x0 = tbuf[(dq * 8 + 2 * i    ) * 132 + p];
                float x1 = tbuf[(dq * 8 + 2 * i + 1) * 132 + p];
                __half h0 = __float2half_rn(x0), h1 = __float2half_rn(x1);
                __half l0 = __float2half_rn(x0 - __half2float(h0));
                __half l1 = __float2half_rn(x1 - __half2float(h1));
                ph[i] = (uint32_t)__half_as_ushort(h0) | ((uint32_t)__half_as_ushort(h1) << 16);
                pl[i] = (uint32_t)__half_as_ushort(l0) | ((uint32_t)__half_as_ushort(l1) << 16);
            }
            int ho = p * XROW + dc * 32 + dq * 8;
            *(uint4*)(Xh + ho) = make_uint4(ph[0], ph[1], ph[2], ph[3]);
            *(uint4*)(Xl + ho) = make_uint4(pl[0], pl[1], pl[2], pl[3]);
        }
        __syncthreads();
    }

    float acc[2][4][4];
    #pragma unroll
    for (int mt = 0; mt < 2; ++mt)
        #pragma unroll
        for (int nt = 0; nt < 4; ++nt)
            #pragma unroll
            for (int j = 0; j < 4; ++j) acc[mt][nt][j] = 0.f;

    // ---- main loop: 32 pieces (8 nc x 4 kc), hi-only MMAs ----
    for (int piece = 0; piece < 32; ++piece) {
        const int nc   = piece >> 2;
        const int kc   = piece & 3;
        const int bsel = piece & 1;
        unsigned short* WhB = (unsigned short*)(smem + (bsel ? OFF_WH1 : OFF_WH0));

        #pragma unroll
        for (int j = 0; j < 2; ++j) {
            int idx = tid + j * NTHREADS;
            int code = idx >> 3, seg = idx & 7;
            *(uint4*)(WhB + code * WROWH + seg * 8) = fh[j];
        }
        if (piece + 1 < 32) {
            int nn = (piece + 1) >> 2, nk = (piece + 1) & 3;
            #pragma unroll
            for (int j = 0; j < 2; ++j) {
                int idx = tid + j * NTHREADS;
                int code = idx >> 3, seg = idx & 7;
                fh[j] = *(const uint4*)(g_whi + (size_t)(nn * 128 + code) * D + nk * 64 + seg * 8);
            }
        }
        __syncthreads();

        const uint32_t wbh = sb + (bsel ? OFF_WH1 : OFF_WH0);
        const uint32_t ao0 = (uint32_t)kc * 128;
        #pragma unroll
        for (int ks = 0; ks < 4; ++ks) {
            uint32_t ah0[4], ah1[4], bh[8];
            uint32_t ao = ao0 + ks * 32;
            ldsm4(ah0, aXh[0] + ao);
            ldsm4(ah1, aXh[1] + ao);
            ldsm4(bh + 0, wbh + rB[0] + ks * 32);
            ldsm4(bh + 4, wbh + rB[1] + ks * 32);
            #pragma unroll
            for (int nt = 0; nt < 4; ++nt) {
                mma16816(acc[0][nt], ah0, &bh[nt * 2]);
                mma16816(acc[1][nt], ah1, &bh[nt * 2]);
            }
        }

        if (kc == 3) {
            // finalize chunk scores in-place: s = acc - 0.5||w||^2
            float cmax[4] = {-1e30f, -1e30f, -1e30f, -1e30f};
            #pragma unroll
            for (int mt = 0; mt < 2; ++mt)
                #pragma unroll
                for (int nt = 0; nt < 4; ++nt)
                    #pragma unroll
                    for (int j = 0; j < 4; ++j) {
                        int nl = wN * 32 + nt * 8 + 2 * t + (j & 1);
                        float s = acc[mt][nt][j] - wsq_s[nc * 128 + nl];
                        acc[mt][nt][j] = s;
                        int slot = mt * 2 + (j >> 1);
                        cmax[slot] = fmaxf(cmax[slot], s);
                    }
            // chunk max across t (lanes sharing positions), stage per wN
            #pragma unroll
            for (int o = 1; o <= 2; o <<= 1)
                #pragma unroll
                for (int s = 0; s < 4; ++s)
                    cmax[s] = fmaxf(cmax[s], __shfl_xor_sync(0xffffffffu, cmax[s], o));
            if (t == 0) {
                #pragma unroll
                for (int s = 0; s < 4; ++s)
                    redv[parr[s] * 4 + wN] = cmax[s];
            }
            __syncthreads();
            if (tid < TP)
                maxv[tid] = fmaxf(maxv[tid],
                    fmaxf(fmaxf(redv[tid * 4], redv[tid * 4 + 1]),
                          fmaxf(redv[tid * 4 + 2], redv[tid * 4 + 3])));
            __syncthreads();
            // push candidates >= running max - eps (superset of final set)
            #pragma unroll
            for (int mt = 0; mt < 2; ++mt)
                #pragma unroll
                for (int nt = 0; nt < 4; ++nt)
                    #pragma unroll
                    for (int j = 0; j < 4; ++j) {
                        int slot = mt * 2 + (j >> 1);
                        float s = acc[mt][nt][j];
                        if (s >= maxv[parr[slot]] - EPSILON) {
                            int k = nc * 128 + wN * 32 + nt * 8 + 2 * t + (j & 1);
                            int idx = atomicAdd(&ctl[0], 1);
                            if (idx < QCAP) qpk[idx] = (parr[slot] << 16) | k;
                        }
                        acc[mt][nt][j] = 0.f;
                    }
        }
    }
    __syncthreads();
    const int nq = (ctl[0] < QCAP) ? ctl[0] : QCAP;

    // ---- warp-cooperative exact rescue: x = xh+xl (2^-22), w fp32 ----
    for (int ci = warp; ci < nq; ci += 16) {
        int pk = qpk[ci];
        int cp = pk >> 16, ck = pk & 1023;
        const float* wr = wgt + (size_t)ck * D;
        float a = 0.f;
        #pragma unroll
        for (int m = 0; m < 8; ++m) {
            int d = lane + 32 * m;
            float xf = __half2float(__ushort_as_half(Xh[cp * XROW + d]))
                     + __half2float(__ushort_as_half(Xl[cp * XROW + d]));
            a = fmaf(xf, wr[d], a);
        }
        #pragma unroll
        for (int o = 16; o > 0; o >>= 1) a += __shfl_xor_sync(0xffffffffu, a, o);
        if (lane == 0) qval[ci] = a - wsq_s[ck];
    }
    __syncthreads();

    // ---- per-position exact argmax over candidates (order-independent) ----
    if (tid < TP) {
        float bv = -1e30f;
        int   bk = 0;
        for (int i = 0; i < nq; ++i) {
            int pk = qpk[i];
            if ((pk >> 16) == tid) {
                float v = qval[i];
                int   k = pk & 1023;
                if (v > bv || (v == bv && k < bk)) { bv = v; bk = k; }
            }
        }
        sidx[tid] = bk;
    }
    __syncthreads();

    // ---- output: gather + NCHW write + loss partial ----
    {
        int p  = tid & 127;
        int ds = tid >> 7;
        int myidx = sidx[p];
        const float4* wrow = (const float4*)(wgt + (size_t)myidx * D);
        float* op = out + (((size_t)b * D) << 10) + hw0 + p;
        const float* xp = xin + p;
        float lsum = 0.f;
        #pragma unroll 4
        for (int i = 0; i < 16; ++i) {
            int gq = ds + (i << 2);
            float4 qv = __ldg(wrow + gq);
            float x0 = xp[((size_t)(4 * gq + 0)) << 10];
            float x1 = xp[((size_t)(4 * gq + 1)) << 10];
            float x2 = xp[((size_t)(4 * gq + 2)) << 10];
            float x3 = xp[((size_t)(4 * gq + 3)) << 10];
            float d0 = qv.x - x0, d1 = qv.y - x1, d2 = qv.z - x2, d3 = qv.w - x3;
            lsum = fmaf(d0, d0, lsum); lsum = fmaf(d1, d1, lsum);
            lsum = fmaf(d2, d2, lsum); lsum = fmaf(d3, d3, lsum);
            op[((size_t)(4 * gq + 0)) << 10] = qv.x;
            op[((size_t)(4 * gq + 1)) << 10] = qv.y;
            op[((size_t)(4 * gq + 2)) << 10] = qv.z;
            op[((size_t)(4 * gq + 3)) << 10] = qv.w;
        }
        sred[tid] = lsum;
    }
    __syncthreads();
    #pragma unroll
    for (int s = NTHREADS / 2; s > 0; s >>= 1) {
        if (tid < s) sred[tid] += sred[tid + s];
        __syncthreads();
    }
    if (tid == 0) g_partial[blockIdx.x] = sred[0];

    // ---- last-block loss finalize (deterministic; counter self-resets) ----
    if (tid == 0) {
        __threadfence();
        int c = atomicAdd(&g_count, 1);
        ctl[1] = (c == NBLOCKS - 1) ? 1 : 0;
    }
    __syncthreads();
    if (ctl[1]) {
        __threadfence();
        sred[tid] = (tid < NBLOCKS) ? g_partial[tid] : 0.f;
        __syncthreads();
        #pragma unroll
        for (int s = NTHREADS / 2; s > 0; s >>= 1) {
            if (tid < s) sred[tid] += sred[tid + s];
            __syncthreads();
        }
        if (tid == 0) {
            out[loss_index] = 1.25f * sred[0] / (float)OUT_ELEMS;
            g_count = 0;
        }
    }
}

extern "C" void kernel_launch(void* const* d_in, const int* in_sizes, int n_in,
                              void* d_out, int out_size)
{
    (void)in_sizes; (void)n_in;
    const float* inp = (const float*)d_in[0];   // [32,256,32,32] fp32 NCHW
    const float* wgt = (const float*)d_in[1];   // [1024,256] fp32
    float* out = (float*)d_out;

    (void)cudaFuncSetAttribute(vq_main, cudaFuncAttributeMaxDynamicSharedMemorySize,
                               SMEM_A);

    vq_prep<<<K / 8, 256>>>(wgt);
    vq_main<<<NBLOCKS, NTHREADS, SMEM_A>>>(inp, wgt, out, out_size - 1);
}